// round 5
// baseline (speedup 1.0000x reference)
#include <cuda_runtime.h>
#include <cuda_fp16.h>
#include <cstdint>

#define BATCH 512
#define INC   1152
#define NC    10
#define DC    16
#define JD    160      // NC*DC
#define NSLOT 80       // half2 slots per (b,i): slot m holds jd {2m, 2m+1}
#define CSZ   8        // cluster CTAs per batch
#define IQ    144      // i-range per route CTA (INC / CSZ)
#define RW    8        // warps per route CTA (256 threads)
#define EPSQ  1e-7f

typedef unsigned long long u64;

// u_hat in fp16, layout [b][i][slot], slot m = jd pair (2m, 2m+1). 188 MB.
__device__ __half2 g_uhat[(size_t)BATCH * INC * NSLOT];

// ---------------------------------------------------------------------------
// helpers
// ---------------------------------------------------------------------------
__device__ __forceinline__ void cluster_sync() {
    asm volatile("barrier.cluster.arrive.aligned;\n\t"
                 "barrier.cluster.wait.aligned;" ::: "memory");
}

__device__ __forceinline__ float peer_f32(const float* p, unsigned int peer) {
    unsigned int a = (unsigned int)__cvta_generic_to_shared(p);
    unsigned int r;
    asm("mapa.shared::cluster.u32 %0, %1, %2;" : "=r"(r) : "r"(a), "r"(peer));
    float v;
    asm volatile("ld.shared::cluster.f32 %0, [%1];" : "=f"(v) : "r"(r));
    return v;
}

__device__ __forceinline__ u64 pack2(float lo, float hi) {
    u64 r;
    asm("mov.b64 %0, {%1, %2};" : "=l"(r) : "f"(lo), "f"(hi));
    return r;
}
__device__ __forceinline__ void fma2(u64& d, u64 a, u64 b) {
    asm("fma.rn.f32x2 %0, %1, %2, %3;" : "=l"(d) : "l"(a), "l"(b), "l"(d));
}
// f32x2 {lo,hi} -> half2 {.x=lo, .y=hi}
__device__ __forceinline__ __half2 f2_to_h2(u64 v) {
    float lo, hi;
    asm("mov.b64 {%0, %1}, %2;" : "=f"(lo), "=f"(hi) : "l"(v));
    unsigned int r;
    asm("cvt.rn.f16x2.f32 %0, %1, %2;" : "=r"(r) : "f"(hi), "f"(lo));
    return *(__half2*)&r;
}

// ---------------------------------------------------------------------------
// Kernel A: u_hat[b,i,jd] = sum_k inputs[b,i,k] * W[jd(i),k], fp16 output.
// Warp owns (i, 64-batch chunk); W pairs packed as f32x2 in registers;
// FFMA2 halves the FMA instruction count. Inputs prefetched one iter ahead.
// ---------------------------------------------------------------------------
__global__ __launch_bounds__(256) void uhat_kernel(const float* __restrict__ inp,
                                                   const float* __restrict__ W) {
    const int warp = threadIdx.x >> 5;
    const int lane = threadIdx.x & 31;
    const int gw = blockIdx.x * 8 + warp;   // [0, 9216)
    const int i = gw >> 3;
    const int chunk = gw & 7;

    // wp?[k] = pack(W[jd0][k], W[jd0+1][k])
    u64 wpA[8], wpB[8], wpC[8];
#define LOADW(dst, jd0)                                                        \
    {                                                                          \
        const int j_ = (jd0) >> 4, d_ = (jd0) & 15;                            \
        const float4* p_ =                                                     \
            (const float4*)(W + (((size_t)j_ * INC + i) * DC + d_) * 8);       \
        float4 q0 = __ldg(p_), q1 = __ldg(p_ + 1), q2 = __ldg(p_ + 2),         \
               q3 = __ldg(p_ + 3);                                             \
        dst[0] = pack2(q0.x, q2.x); dst[1] = pack2(q0.y, q2.y);                \
        dst[2] = pack2(q0.z, q2.z); dst[3] = pack2(q0.w, q2.w);                \
        dst[4] = pack2(q1.x, q3.x); dst[5] = pack2(q1.y, q3.y);                \
        dst[6] = pack2(q1.z, q3.z); dst[7] = pack2(q1.w, q3.w);                \
    }
    LOADW(wpA, 2 * lane);
    LOADW(wpB, 64 + 2 * lane);
    if (lane < 16) {
        LOADW(wpC, 128 + 2 * lane);
    } else {
#pragma unroll
        for (int k = 0; k < 8; k++) wpC[k] = 0ull;
    }
#undef LOADW

    const int b0 = chunk * 64;
    const float4* ip0 = (const float4*)(inp + ((size_t)b0 * INC + i) * 8);
    float4 x = __ldg(ip0), y = __ldg(ip0 + 1);
#pragma unroll 2
    for (int bb = 0; bb < 64; bb++) {
        u64 in2[8];
        in2[0] = pack2(x.x, x.x); in2[1] = pack2(x.y, x.y);
        in2[2] = pack2(x.z, x.z); in2[3] = pack2(x.w, x.w);
        in2[4] = pack2(y.x, y.x); in2[5] = pack2(y.y, y.y);
        in2[6] = pack2(y.z, y.z); in2[7] = pack2(y.w, y.w);
        if (bb + 1 < 64) {  // prefetch next batch's inputs
            const float4* ipn =
                (const float4*)(inp + ((size_t)(b0 + bb + 1) * INC + i) * 8);
            x = __ldg(ipn);
            y = __ldg(ipn + 1);
        }

        u64 aA = 0ull, aB = 0ull, aC = 0ull;
#pragma unroll
        for (int k = 0; k < 8; k++) {
            fma2(aA, in2[k], wpA[k]);
            fma2(aB, in2[k], wpB[k]);
            fma2(aC, in2[k], wpC[k]);
        }
        __half2* up = g_uhat + ((size_t)(b0 + bb) * INC + i) * NSLOT;
        up[lane] = f2_to_h2(aA);
        up[32 + lane] = f2_to_h2(aB);
        if (lane < 16) up[64 + lane] = f2_to_h2(aC);
    }
}

// ---------------------------------------------------------------------------
// Kernel R: routing. Cluster of 8 CTAs per batch; each CTA caches its 144-i
// slice of u_hat[b] in smem (46 KB fp16) while accumulating pass-0's uniform
// sum, then runs passes 1,2 from smem. ~53 KB smem, 256 thr -> 4 CTAs/SM.
// Lane layout: lanes 0..19 active, lane l owns half2 slots 4l..4l+3 (16B),
// all within j = l>>1; pair-shuffle(xor 1) completes the d-dot.
// ---------------------------------------------------------------------------
__global__ __launch_bounds__(256, 4) __cluster_dims__(CSZ, 1, 1)
void route_kernel(float* __restrict__ out) {
    extern __shared__ char smraw[];
    __half2* Usm = (__half2*)smraw;                            // IQ*80 half2
    float* red = (float*)(smraw + (size_t)IQ * NSLOT * 4);     // RW*160
    float* sfin = red + RW * JD;                               // 160 (DSMEM)
    float* stot = sfin + JD;                                   // 160
    float* Vsm = stot + JD;                                    // 160
    float* scl = Vsm + JD;                                     // 16

    const int tid = threadIdx.x;
    const int warp = tid >> 5;
    const int lane = tid & 31;
    const int b = blockIdx.x / CSZ;
    const unsigned int rank = blockIdx.x % CSZ;
    const bool act = (lane < 20);
    const int sl = act ? 4 * lane : 0;
    float2* red2 = (float2*)red;

    const __half2* gsrc = g_uhat + ((size_t)b * INC + rank * IQ) * NSLOT;

    // ---- stream u_hat slice -> smem, accumulate pass-0 (c = 0.1) ----
    float2 a0 = make_float2(0.f, 0.f), a1 = a0, a2 = a0, a3 = a0;
    if (act) {
#pragma unroll 2
        for (int i = warp; i < IQ; i += RW) {
            uint4 u = *(const uint4*)(gsrc + (size_t)i * NSLOT + sl);
            *(uint4*)(Usm + (size_t)i * NSLOT + sl) = u;
            __half2 h0 = *(__half2*)&u.x, h1 = *(__half2*)&u.y;
            __half2 h2 = *(__half2*)&u.z, h3 = *(__half2*)&u.w;
            float2 f0 = __half22float2(h0), f1 = __half22float2(h1);
            float2 f2 = __half22float2(h2), f3 = __half22float2(h3);
            a0.x += f0.x; a0.y += f0.y; a1.x += f1.x; a1.y += f1.y;
            a2.x += f2.x; a2.y += f2.y; a3.x += f3.x; a3.y += f3.y;
        }
        red2[warp * 80 + sl + 0] = a0;
        red2[warp * 80 + sl + 1] = a1;
        red2[warp * 80 + sl + 2] = a2;
        red2[warp * 80 + sl + 3] = a3;
    }
    __syncthreads();
    if (tid < JD) {
        float s = 0.f;
#pragma unroll
        for (int w = 0; w < RW; w++) s += red[w * JD + tid];
        sfin[tid] = s;
    }
    __syncthreads();
    cluster_sync();
    if (tid < JD) {
        float s = sfin[tid];
#pragma unroll
        for (unsigned int r = 1; r < CSZ; r++)
            s += peer_f32(sfin + tid, rank ^ r);
        stot[tid] = 0.1f * s;
    }
    __syncthreads();
    if (tid < NC) {
        float sq = 0.f;
#pragma unroll
        for (int d = 0; d < DC; d++) {
            float v = stot[tid * DC + d];
            sq = fmaf(v, v, sq);
        }
        scl[tid] = sq / ((1.0f + sq) * sqrtf(sq + EPSQ));
    }
    __syncthreads();
    if (tid < JD) Vsm[tid] = scl[tid >> 4] * stot[tid];
    __syncthreads();
    cluster_sync();  // peers done reading sfin; Vsm ready

    // ---- passes 1,2 from smem ----
    for (int p = 1; p <= 2; p++) {
        const float2* V2 = (const float2*)Vsm;
        float2 v0 = V2[sl], v1 = V2[sl + 1], v2 = V2[sl + 2], v3 = V2[sl + 3];
        float2 s0 = make_float2(0.f, 0.f), s1 = s0, s2 = s0, s3 = s0;
#pragma unroll 2
        for (int i = warp; i < IQ; i += RW) {
            uint4 u = *(const uint4*)(Usm + (size_t)i * NSLOT + sl);
            __half2 h0 = *(__half2*)&u.x, h1 = *(__half2*)&u.y;
            __half2 h2 = *(__half2*)&u.z, h3 = *(__half2*)&u.w;
            float2 f0 = __half22float2(h0), f1 = __half22float2(h1);
            float2 f2 = __half22float2(h2), f3 = __half22float2(h3);

            float t = f0.x * v0.x + f0.y * v0.y;
            t = fmaf(f1.x, v1.x, t); t = fmaf(f1.y, v1.y, t);
            t = fmaf(f2.x, v2.x, t); t = fmaf(f2.y, v2.y, t);
            t = fmaf(f3.x, v3.x, t); t = fmaf(f3.y, v3.y, t);
            t += __shfl_xor_sync(0xffffffffu, t, 1);  // full dot, j = lane>>1

            // |t| < ~4 -> no max-subtraction needed
            float e = act ? __expf(t) : 0.f;
            float sv = e;
            sv += __shfl_xor_sync(0xffffffffu, sv, 2);
            sv += __shfl_xor_sync(0xffffffffu, sv, 4);
            sv += __shfl_xor_sync(0xffffffffu, sv, 8);
            sv += __shfl_xor_sync(0xffffffffu, sv, 16);  // = sum_j e_j exactly
            float c = e * __fdividef(1.f, sv);

            s0.x = fmaf(c, f0.x, s0.x); s0.y = fmaf(c, f0.y, s0.y);
            s1.x = fmaf(c, f1.x, s1.x); s1.y = fmaf(c, f1.y, s1.y);
            s2.x = fmaf(c, f2.x, s2.x); s2.y = fmaf(c, f2.y, s2.y);
            s3.x = fmaf(c, f3.x, s3.x); s3.y = fmaf(c, f3.y, s3.y);
        }
        if (act) {
            red2[warp * 80 + sl + 0] = s0;
            red2[warp * 80 + sl + 1] = s1;
            red2[warp * 80 + sl + 2] = s2;
            red2[warp * 80 + sl + 3] = s3;
        }
        __syncthreads();
        if (tid < JD) {
            float s = 0.f;
#pragma unroll
            for (int w = 0; w < RW; w++) s += red[w * JD + tid];
            sfin[tid] = s;
        }
        __syncthreads();
        cluster_sync();
        if (tid < JD) {
            float s = sfin[tid];
#pragma unroll
            for (unsigned int r = 1; r < CSZ; r++)
                s += peer_f32(sfin + tid, rank ^ r);
            stot[tid] = s;
        }
        __syncthreads();
        if (tid < NC) {
            float sq = 0.f;
#pragma unroll
            for (int d = 0; d < DC; d++) {
                float v = stot[tid * DC + d];
                sq = fmaf(v, v, sq);
            }
            scl[tid] = sq / ((1.0f + sq) * sqrtf(sq + EPSQ));
        }
        __syncthreads();
        if (p == 1) {
            if (tid < JD) Vsm[tid] += scl[tid >> 4] * stot[tid];
            __syncthreads();
        } else {
            if (rank == 0 && tid < JD)
                out[(size_t)b * JD + tid] = scl[tid >> 4] * stot[tid];
        }
        cluster_sync();  // sfin reuse / exit safety
    }
}

// ---------------------------------------------------------------------------
extern "C" void kernel_launch(void* const* d_in, const int* in_sizes, int n_in,
                              void* d_out, int out_size) {
    const float* inputs = (const float*)d_in[0];  // [512, 1152, 8]
    const float* W = (const float*)d_in[1];       // [10, 1152, 16, 8]
    float* out = (float*)d_out;                   // [512, 10, 16]

    uhat_kernel<<<INC, 256>>>(inputs, W);

    const int smem = IQ * NSLOT * 4 + (RW * JD + 3 * JD + 16) * 4;  // ~53 KB
    cudaFuncSetAttribute(route_kernel,
                         cudaFuncAttributeMaxDynamicSharedMemorySize, smem);
    route_kernel<<<BATCH * CSZ, 256, smem>>>(out);
}

// round 6
// speedup vs baseline: 1.3553x; 1.3553x over previous
#include <cuda_runtime.h>
#include <cuda_fp16.h>
#include <cstdint>

#define BATCH 512
#define INC   1152
#define NC    10
#define DC    16
#define JD    160      // NC*DC
#define NSLOT 80       // half2 slots per (b,i): slot m holds jd {2m, 2m+1}
#define CSZ   4        // cluster CTAs per batch
#define IQ    288      // i-range per route CTA (INC / CSZ)
#define RW    12       // warps per route CTA (384 threads)
#define EPSQ  1e-7f

typedef unsigned long long u64;

// u_hat in fp16, layout [b][i][slot], slot m = jd pair (2m, 2m+1). 188 MB.
__device__ __half2 g_uhat[(size_t)BATCH * INC * NSLOT];

// ---------------------------------------------------------------------------
// helpers
// ---------------------------------------------------------------------------
__device__ __forceinline__ void cluster_sync() {
    asm volatile("barrier.cluster.arrive.aligned;\n\t"
                 "barrier.cluster.wait.aligned;" ::: "memory");
}

__device__ __forceinline__ float peer_f32(const float* p, unsigned int peer) {
    unsigned int a = (unsigned int)__cvta_generic_to_shared(p);
    unsigned int r;
    asm("mapa.shared::cluster.u32 %0, %1, %2;" : "=r"(r) : "r"(a), "r"(peer));
    float v;
    asm volatile("ld.shared::cluster.f32 %0, [%1];" : "=f"(v) : "r"(r));
    return v;
}

__device__ __forceinline__ u64 pack2(float lo, float hi) {
    u64 r;
    asm("mov.b64 %0, {%1, %2};" : "=l"(r) : "f"(lo), "f"(hi));
    return r;
}
__device__ __forceinline__ void fma2(u64& d, u64 a, u64 b) {
    asm("fma.rn.f32x2 %0, %1, %2, %3;" : "=l"(d) : "l"(a), "l"(b), "l"(d));
}
// f32x2 {lo,hi} -> half2 {.x=lo, .y=hi}
__device__ __forceinline__ __half2 f2_to_h2(u64 v) {
    float lo, hi;
    asm("mov.b64 {%0, %1}, %2;" : "=f"(lo), "=f"(hi) : "l"(v));
    unsigned int r;
    asm("cvt.rn.f16x2.f32 %0, %1, %2;" : "=r"(r) : "f"(hi), "f"(lo));
    return *(__half2*)&r;
}

// ---------------------------------------------------------------------------
// Kernel A: u_hat[b,i,jd] = sum_k inputs[b,i,k] * W[jd(i),k], fp16 output.
// Warp owns (i, 64-batch chunk); W pairs packed as f32x2 in registers;
// FFMA2 halves the FMA instruction count. Inputs prefetched one iter ahead.
// ---------------------------------------------------------------------------
__global__ __launch_bounds__(256) void uhat_kernel(const float* __restrict__ inp,
                                                   const float* __restrict__ W) {
    const int warp = threadIdx.x >> 5;
    const int lane = threadIdx.x & 31;
    const int gw = blockIdx.x * 8 + warp;   // [0, 9216)
    const int i = gw >> 3;
    const int chunk = gw & 7;

    // wp?[k] = pack(W[jd0][k], W[jd0+1][k])
    u64 wpA[8], wpB[8], wpC[8];
#define LOADW(dst, jd0)                                                        \
    {                                                                          \
        const int j_ = (jd0) >> 4, d_ = (jd0) & 15;                            \
        const float4* p_ =                                                     \
            (const float4*)(W + (((size_t)j_ * INC + i) * DC + d_) * 8);       \
        float4 q0 = __ldg(p_), q1 = __ldg(p_ + 1), q2 = __ldg(p_ + 2),         \
               q3 = __ldg(p_ + 3);                                             \
        dst[0] = pack2(q0.x, q2.x); dst[1] = pack2(q0.y, q2.y);                \
        dst[2] = pack2(q0.z, q2.z); dst[3] = pack2(q0.w, q2.w);                \
        dst[4] = pack2(q1.x, q3.x); dst[5] = pack2(q1.y, q3.y);                \
        dst[6] = pack2(q1.z, q3.z); dst[7] = pack2(q1.w, q3.w);                \
    }
    LOADW(wpA, 2 * lane);
    LOADW(wpB, 64 + 2 * lane);
    if (lane < 16) {
        LOADW(wpC, 128 + 2 * lane);
    } else {
#pragma unroll
        for (int k = 0; k < 8; k++) wpC[k] = 0ull;
    }
#undef LOADW

    const int b0 = chunk * 64;
    const float4* ip0 = (const float4*)(inp + ((size_t)b0 * INC + i) * 8);
    float4 x = __ldg(ip0), y = __ldg(ip0 + 1);
#pragma unroll 2
    for (int bb = 0; bb < 64; bb++) {
        u64 in2[8];
        in2[0] = pack2(x.x, x.x); in2[1] = pack2(x.y, x.y);
        in2[2] = pack2(x.z, x.z); in2[3] = pack2(x.w, x.w);
        in2[4] = pack2(y.x, y.x); in2[5] = pack2(y.y, y.y);
        in2[6] = pack2(y.z, y.z); in2[7] = pack2(y.w, y.w);
        if (bb + 1 < 64) {  // prefetch next batch's inputs
            const float4* ipn =
                (const float4*)(inp + ((size_t)(b0 + bb + 1) * INC + i) * 8);
            x = __ldg(ipn);
            y = __ldg(ipn + 1);
        }

        u64 aA = 0ull, aB = 0ull, aC = 0ull;
#pragma unroll
        for (int k = 0; k < 8; k++) {
            fma2(aA, in2[k], wpA[k]);
            fma2(aB, in2[k], wpB[k]);
            fma2(aC, in2[k], wpC[k]);
        }
        __half2* up = g_uhat + ((size_t)(b0 + bb) * INC + i) * NSLOT;
        up[lane] = f2_to_h2(aA);
        up[32 + lane] = f2_to_h2(aB);
        if (lane < 16) up[64 + lane] = f2_to_h2(aC);
    }
}

// ---------------------------------------------------------------------------
// Kernel R: routing. Cluster of 4 CTAs per batch; each CTA caches its 288-i
// quarter of u_hat[b] in smem (92 KB fp16) while accumulating pass-0's uniform
// sum, then runs passes 1,2 from smem. ~102 KB smem -> 2 CTAs/SM (24 warps).
// Lane layout: lanes 0..19 active, lane l owns half2 slots 4l..4l+3 (16B),
// all within j = l>>1; pair-shuffle(xor 1) completes the d-dot.
// ---------------------------------------------------------------------------
__global__ __launch_bounds__(384, 2) __cluster_dims__(CSZ, 1, 1)
void route_kernel(float* __restrict__ out) {
    extern __shared__ char smraw[];
    __half2* Usm = (__half2*)smraw;                            // IQ*80 half2
    float* red = (float*)(smraw + (size_t)IQ * NSLOT * 4);     // RW*160
    float* sfin = red + RW * JD;                               // 160 (DSMEM)
    float* stot = sfin + JD;                                   // 160
    float* Vsm = stot + JD;                                    // 160
    float* scl = Vsm + JD;                                     // 16

    const int tid = threadIdx.x;
    const int warp = tid >> 5;
    const int lane = tid & 31;
    const int b = blockIdx.x >> 2;
    const unsigned int rank = blockIdx.x & 3;
    const bool act = (lane < 20);
    const int sl = act ? 4 * lane : 0;
    float2* red2 = (float2*)red;

    const __half2* gsrc = g_uhat + ((size_t)b * INC + rank * IQ) * NSLOT;

    // ---- stream u_hat quarter -> smem, accumulate pass-0 (c = 0.1) ----
    float2 a0 = make_float2(0.f, 0.f), a1 = a0, a2 = a0, a3 = a0;
    if (act) {
#pragma unroll 2
        for (int i = warp; i < IQ; i += RW) {
            uint4 u = *(const uint4*)(gsrc + (size_t)i * NSLOT + sl);
            *(uint4*)(Usm + (size_t)i * NSLOT + sl) = u;
            __half2 h0 = *(__half2*)&u.x, h1 = *(__half2*)&u.y;
            __half2 h2 = *(__half2*)&u.z, h3 = *(__half2*)&u.w;
            float2 f0 = __half22float2(h0), f1 = __half22float2(h1);
            float2 f2 = __half22float2(h2), f3 = __half22float2(h3);
            a0.x += f0.x; a0.y += f0.y; a1.x += f1.x; a1.y += f1.y;
            a2.x += f2.x; a2.y += f2.y; a3.x += f3.x; a3.y += f3.y;
        }
        red2[warp * 80 + sl + 0] = a0;
        red2[warp * 80 + sl + 1] = a1;
        red2[warp * 80 + sl + 2] = a2;
        red2[warp * 80 + sl + 3] = a3;
    }
    __syncthreads();
    if (tid < JD) {
        float s = 0.f;
#pragma unroll
        for (int w = 0; w < RW; w++) s += red[w * JD + tid];
        sfin[tid] = s;
    }
    __syncthreads();
    cluster_sync();
    if (tid < JD) {
        float s = sfin[tid];
#pragma unroll
        for (unsigned int r = 1; r < CSZ; r++)
            s += peer_f32(sfin + tid, rank ^ r);
        stot[tid] = 0.1f * s;
    }
    __syncthreads();
    if (tid < NC) {
        float sq = 0.f;
#pragma unroll
        for (int d = 0; d < DC; d++) {
            float v = stot[tid * DC + d];
            sq = fmaf(v, v, sq);
        }
        scl[tid] = sq / ((1.0f + sq) * sqrtf(sq + EPSQ));
    }
    __syncthreads();
    if (tid < JD) Vsm[tid] = scl[tid >> 4] * stot[tid];
    __syncthreads();
    cluster_sync();  // peers done reading sfin; Vsm ready

    // ---- passes 1,2 from smem ----
    for (int p = 1; p <= 2; p++) {
        const float2* V2 = (const float2*)Vsm;
        float2 v0 = V2[sl], v1 = V2[sl + 1], v2 = V2[sl + 2], v3 = V2[sl + 3];
        float2 s0 = make_float2(0.f, 0.f), s1 = s0, s2 = s0, s3 = s0;
#pragma unroll 4
        for (int i = warp; i < IQ; i += RW) {
            uint4 u = *(const uint4*)(Usm + (size_t)i * NSLOT + sl);
            __half2 h0 = *(__half2*)&u.x, h1 = *(__half2*)&u.y;
            __half2 h2 = *(__half2*)&u.z, h3 = *(__half2*)&u.w;
            float2 f0 = __half22float2(h0), f1 = __half22float2(h1);
            float2 f2 = __half22float2(h2), f3 = __half22float2(h3);

            float t = f0.x * v0.x + f0.y * v0.y;
            t = fmaf(f1.x, v1.x, t); t = fmaf(f1.y, v1.y, t);
            t = fmaf(f2.x, v2.x, t); t = fmaf(f2.y, v2.y, t);
            t = fmaf(f3.x, v3.x, t); t = fmaf(f3.y, v3.y, t);
            t += __shfl_xor_sync(0xffffffffu, t, 1);  // full dot, j = lane>>1

            // |t| < ~4 -> no max-subtraction needed
            float e = act ? __expf(t) : 0.f;
            float sv = e;
            sv += __shfl_xor_sync(0xffffffffu, sv, 2);
            sv += __shfl_xor_sync(0xffffffffu, sv, 4);
            sv += __shfl_xor_sync(0xffffffffu, sv, 8);
            sv += __shfl_xor_sync(0xffffffffu, sv, 16);  // = sum_j e_j exactly
            float c = e * __fdividef(1.f, sv);

            s0.x = fmaf(c, f0.x, s0.x); s0.y = fmaf(c, f0.y, s0.y);
            s1.x = fmaf(c, f1.x, s1.x); s1.y = fmaf(c, f1.y, s1.y);
            s2.x = fmaf(c, f2.x, s2.x); s2.y = fmaf(c, f2.y, s2.y);
            s3.x = fmaf(c, f3.x, s3.x); s3.y = fmaf(c, f3.y, s3.y);
        }
        if (act) {
            red2[warp * 80 + sl + 0] = s0;
            red2[warp * 80 + sl + 1] = s1;
            red2[warp * 80 + sl + 2] = s2;
            red2[warp * 80 + sl + 3] = s3;
        }
        __syncthreads();
        if (tid < JD) {
            float s = 0.f;
#pragma unroll
            for (int w = 0; w < RW; w++) s += red[w * JD + tid];
            sfin[tid] = s;
        }
        __syncthreads();
        cluster_sync();
        if (tid < JD) {
            float s = sfin[tid];
#pragma unroll
            for (unsigned int r = 1; r < CSZ; r++)
                s += peer_f32(sfin + tid, rank ^ r);
            stot[tid] = s;
        }
        __syncthreads();
        if (tid < NC) {
            float sq = 0.f;
#pragma unroll
            for (int d = 0; d < DC; d++) {
                float v = stot[tid * DC + d];
                sq = fmaf(v, v, sq);
            }
            scl[tid] = sq / ((1.0f + sq) * sqrtf(sq + EPSQ));
        }
        __syncthreads();
        if (p == 1) {
            if (tid < JD) Vsm[tid] += scl[tid >> 4] * stot[tid];
            __syncthreads();
        } else {
            if (rank == 0 && tid < JD)
                out[(size_t)b * JD + tid] = scl[tid >> 4] * stot[tid];
        }
        cluster_sync();  // sfin reuse / exit safety
    }
}

// ---------------------------------------------------------------------------
extern "C" void kernel_launch(void* const* d_in, const int* in_sizes, int n_in,
                              void* d_out, int out_size) {
    const float* inputs = (const float*)d_in[0];  // [512, 1152, 8]
    const float* W = (const float*)d_in[1];       // [10, 1152, 16, 8]
    float* out = (float*)d_out;                   // [512, 10, 16]

    uhat_kernel<<<INC, 256>>>(inputs, W);

    const int smem = IQ * NSLOT * 4 + (RW * JD + 3 * JD + 16) * 4;  // ~102 KB
    cudaFuncSetAttribute(route_kernel,
                         cudaFuncAttributeMaxDynamicSharedMemorySize, smem);
    route_kernel<<<BATCH * CSZ, 384, smem>>>(out);
}